// round 16
// baseline (speedup 1.0000x reference)
#include <cuda_runtime.h>
#include <cuda_fp16.h>
#include <cstdint>

// ---------------------------------------------------------------------------
// SchNet fused kernel, round 16: round-15 + barrier-free tile loop.
// cfconv partials go straight into vs via SMEM atomicAdd (vs zeroed per
// interaction); no red buffer, no pair barriers. 256 thr, 2 CTAs/SM.
// ---------------------------------------------------------------------------

typedef unsigned long long u64;
typedef unsigned int u32;

#define LDA 72   // float stride: Xl
#define LDX 68   // X / vs stride

// float offsets
#define OFF_POS   0        // 256
#define OFF_BIAS  256      // 128
#define OFF_XL    384      // 64*72 = 4608
#define OFF_X     4992     // 4352
#define OFF_VS    9344     // 4352
#define OFF_B1    13696    // 2048 (fp16 frag-major weights)
#define OFF_B2    15744    // 2048
#define OFF_RED   17792    // 64 (head reduce scratch only)
#define OFF_SCR   19840    // 4096: Af frags [0..2048), aux [2048..4096)
#define SMEM_FLOATS 23936
#define SMEM_BYTES  (SMEM_FLOATS * 4)   // 95744 -> 2 CTAs/SM

__device__ __forceinline__ float tanhf_mufu(float x) {
    float r; asm("tanh.approx.f32 %0, %1;" : "=f"(r) : "f"(x)); return r;
}
__device__ __forceinline__ u32 cvt_h2(float lo, float hi) {
    u32 r; asm("cvt.rn.f16x2.f32 %0, %1, %2;" : "=r"(r) : "f"(hi), "f"(lo));
    return r;
}
__device__ __forceinline__ u32 tanh_h2(float lo, float hi) {
    u32 p = cvt_h2(lo, hi), r;
    asm("tanh.approx.f16x2 %0, %1;" : "=r"(r) : "r"(p));
    return r;
}
__device__ __forceinline__ u32 ex2_h2f(float lo, float hi) {
    u32 p = cvt_h2(lo, hi), r;
    asm("ex2.approx.f16x2 %0, %1;" : "=r"(r) : "r"(p));
    return r;
}
__device__ __forceinline__ float2 h2_f2(u32 v) {
    __half2 h = *reinterpret_cast<__half2*>(&v);
    return __half22float2(h);
}
__device__ __forceinline__ void mma_f16(float (&d)[4], u32 a0, u32 a1, u32 a2,
                                        u32 a3, u32 b0, u32 b1) {
    asm("mma.sync.aligned.m16n8k16.row.col.f32.f16.f16.f32 "
        "{%0,%1,%2,%3}, {%4,%5,%6,%7}, {%8,%9}, {%0,%1,%2,%3};"
        : "+f"(d[0]), "+f"(d[1]), "+f"(d[2]), "+f"(d[3])
        : "r"(a0), "r"(a1), "r"(a2), "r"(a3), "r"(b0), "r"(b1));
}

// W[k][n] (64x64 row-major) -> fp16 frag-major B layout (proven); 256 thr
__device__ __forceinline__ void stage_bh(const float* __restrict__ g,
                                         __half* __restrict__ s, int tid) {
#pragma unroll
    for (int ii = 0; ii < 16; ii++) {
        int idx = tid + ii * 256;
        int k = idx >> 6, n = idx & 63;
        int ln = 4 * (n & 7) + ((k >> 1) & 3);
        int i = k >> 3;
        s[((((n >> 3) * 2 + (i >> 2)) * 32 + ln) * 4 + (i & 3)) * 2 + (k & 1)] =
            __float2half(__ldg(g + idx));
    }
}

// fp32 row-major S (64x64, stride lds) -> fp16 A-fragment layout
__device__ __forceinline__ void stage_af(const float* __restrict__ S, int lds,
                                         u32* __restrict__ Au, int tid) {
#pragma unroll
    for (int ii = 0; ii < 8; ii++) {
        int idx = tid + ii * 256;
        int slot = idx & 3, ln = (idx >> 2) & 31;
        int kb = (idx >> 7) & 3, mb = idx >> 9;
        int gg = ln >> 2, tg = ln & 3;
        int row = 16 * mb + gg + 8 * (slot & 1);
        int kk = 16 * kb + 2 * tg + 8 * (slot >> 1);
        Au[idx] = cvt_h2(S[row * lds + kk], S[row * lds + kk + 1]);
    }
}

// 64x64 @ 64x64 fp16 MMA GEMM. 8 warps: wm = m-block, nh = n-half.
template <int EPI>
__device__ __forceinline__ void mma_small(const uint4* __restrict__ Af,
                                          const __half* __restrict__ Bh,
                                          const float* __restrict__ bias_g,
                                          float* __restrict__ C, int ldc,
                                          u32* __restrict__ AfOut,
                                          int wid, int lane) {
    const int wm = wid & 3, nh = wid >> 2;
    const int g = lane >> 2, tig = lane & 3;
    const uint4* ap = Af + wm * 128 + lane;
    uint4 A0 = ap[0], A1 = ap[32], A2 = ap[64], A3 = ap[96];
    const uint4* bp = (const uint4*)Bh + lane;
    const int r0 = 16 * wm + g, r1 = r0 + 8;
#pragma unroll
    for (int nl = 0; nl < 4; nl++) {
        const int nb = 4 * nh + nl;
        uint4 w0 = bp[(nb * 2 + 0) * 32];
        uint4 w1 = bp[(nb * 2 + 1) * 32];
        float d[4] = {0.f, 0.f, 0.f, 0.f};
        mma_f16(d, A0.x, A0.y, A0.z, A0.w, w0.x, w0.y);
        mma_f16(d, A1.x, A1.y, A1.z, A1.w, w0.z, w0.w);
        mma_f16(d, A2.x, A2.y, A2.z, A2.w, w1.x, w1.y);
        mma_f16(d, A3.x, A3.y, A3.z, A3.w, w1.z, w1.w);
        float2 bb = *(const float2*)(bias_g + 8 * nb + 2 * tig);
        if (EPI == 1) {
            u32 base = ((u32)(wm * 4 + (nb >> 1)) * 32 + (u32)lane) * 4 +
                       (u32)(nb & 1) * 2;
            AfOut[base]     = tanh_h2(d[0] + bb.x, d[1] + bb.y);
            AfOut[base + 1] = tanh_h2(d[2] + bb.x, d[3] + bb.y);
        } else {
            const int c = 8 * nb + 2 * tig;
            float2 o0 = make_float2(d[0] + bb.x, d[1] + bb.y);
            float2 o1 = make_float2(d[2] + bb.x, d[3] + bb.y);
            if (EPI == 2) {
                float2 e0 = *(float2*)&C[r0 * ldc + c];
                float2 e1 = *(float2*)&C[r1 * ldc + c];
                o0.x += e0.x; o0.y += e0.y; o1.x += e1.x; o1.y += e1.y;
            }
            *(float2*)&C[r0 * ldc + c] = o0;
            *(float2*)&C[r1 * ldc + c] = o1;
        }
    }
}

__global__ void __launch_bounds__(256, 2)
schnet_kernel(const float* __restrict__ r_g, const float* __restrict__ v1_g,
              const float* __restrict__ v2_g, const float* __restrict__ cen_g,
              const float* __restrict__ Wx_g,  const float* __restrict__ bx_g,
              const float* __restrict__ Wf1_g, const float* __restrict__ bf1_g,
              const float* __restrict__ Wf2_g, const float* __restrict__ bf2_g,
              const float* __restrict__ Wv1_g, const float* __restrict__ bv1_g,
              const float* __restrict__ Wv2_g, const float* __restrict__ bv2_g,
              const float* __restrict__ W1_g,  const float* __restrict__ b1_g,
              const float* __restrict__ W2_g,  const float* __restrict__ b2_g,
              float* __restrict__ out_g) {
    extern __shared__ float sm[];
    float*  pos    = sm + OFF_POS;
    float*  bias_s = sm + OFF_BIAS;
    float*  Xl     = sm + OFF_XL;
    float*  X      = sm + OFF_X;
    float*  vs     = sm + OFF_VS;
    __half* B1h    = (__half*)(sm + OFF_B1);
    __half* B2h    = (__half*)(sm + OFF_B2);
    float*  red    = sm + OFF_RED;
    float*  scr    = sm + OFF_SCR;
    u32*    Af     = (u32*)scr;
    u32*    Af2    = (u32*)(scr + 2048);
    __half* WxH    = (__half*)(scr + 2048);   // aliases Af2; disjoint in time

    const int tid  = threadIdx.x, b = blockIdx.x;
    const int wid  = tid >> 5, lane = tid & 31;
    const int pair = wid >> 1;            // atom-within-tile (0..3)
    const int wm2  = wid & 1;             // row-half of atom
    const int g    = lane >> 2, tig = lane & 3;

    // ---- init ----
    if (tid < 192) pos[tid] = r_g[b * 192 + tid];
#pragma unroll
    for (int ii = 0; ii < 16; ii++) {
        int idx = tid + ii * 256;
        int a = idx >> 6, f = idx & 63;
        X[a * LDX + f] = (a < 2) ? __ldg(v1_g + f) : __ldg(v2_g + f);
    }
    __syncthreads();

    const uint4* b1p = (const uint4*)B1h + lane;
    const uint4* b2p = (const uint4*)B2h + lane;

    // lane's four row positions within the atom's 64 pair-rows
    const int mA0 = 32 * wm2 + g;
    const int mA1 = mA0 + 8;
    const int mB0 = mA0 + 16;
    const int mB1 = mA0 + 24;             // can be pad=63
    const bool pad = (mB1 == 63);

    for (int t = 0; t < 3; t++) {
        const int wofs = t * 4096, bofs = t * 64;

        // stage: Wx (fp16 B-frags), X (fp16 A-frags), Wf1/Wf2, biases; zero vs
        stage_bh(Wx_g + wofs, WxH, tid);
        stage_af(X, LDX, Af, tid);
        stage_bh(Wf1_g + wofs, B1h, tid);
        stage_bh(Wf2_g + wofs, B2h, tid);
        if (tid < 64) {
            bias_s[tid]      = __ldg(bf1_g + bofs + tid);
            bias_s[64 + tid] = __ldg(bf2_g + bofs + tid);
        }
#pragma unroll
        for (int ii = 0; ii < 17; ii++) {
            int idx = tid + ii * 256;
            if (idx < 64 * LDX) vs[idx] = 0.0f;
        }
        __syncthreads();
        // Xl = X@Wx + bx (MMA)
        mma_small<0>((const uint4*)Af, WxH, bx_g + bofs, Xl, LDA, 0, wid, lane);
        __syncthreads();

        // ---- 16 tiles x 4 atoms; NO synchronization inside the loop ----
        for (int tt = 0; tt < 16; tt++) {
            const int ia = 4 * tt + pair;

            const int jA0 = mA0 + (mA0 >= ia);
            const int jA1 = mA1 + (mA1 >= ia);
            const int jB0 = mB0 + (mB0 >= ia);
            const int jB1 = pad ? 63 : mB1 + (mB1 >= ia);

            // distances + quadratic rbf coefficients
            float A0, B0, A1, B1c, A2, B2c, A3, B3;
            {
                float px = pos[3 * ia], py = pos[3 * ia + 1], pz = pos[3 * ia + 2];
                float dx, dy, dz, d;
                dx = px - pos[3 * jA0]; dy = py - pos[3 * jA0 + 1]; dz = pz - pos[3 * jA0 + 2];
                d = sqrtf(fmaf(dx, dx, fmaf(dy, dy, dz * dz)));
                A0 = -14.4269504f * d * d; B0 = 28.8539008f * d;
                dx = px - pos[3 * jA1]; dy = py - pos[3 * jA1 + 1]; dz = pz - pos[3 * jA1 + 2];
                d = sqrtf(fmaf(dx, dx, fmaf(dy, dy, dz * dz)));
                A1 = -14.4269504f * d * d; B1c = 28.8539008f * d;
                dx = px - pos[3 * jB0]; dy = py - pos[3 * jB0 + 1]; dz = pz - pos[3 * jB0 + 2];
                d = sqrtf(fmaf(dx, dx, fmaf(dy, dy, dz * dz)));
                A2 = -14.4269504f * d * d; B2c = 28.8539008f * d;
                dx = px - pos[3 * jB1]; dy = py - pos[3 * jB1 + 1]; dz = pz - pos[3 * jB1 + 2];
                d = pad ? 1e9f : sqrtf(fmaf(dx, dx, fmaf(dy, dy, dz * dz)));
                A3 = -14.4269504f * d * d; B3 = 28.8539008f * d;
            }

            // rbf into fp16x2 A-fragments
            u32 raA0[8], raA1[8], raB0[8], raB1[8];
#pragma unroll
            for (int u = 0; u < 8; u++) {
                int kb = u >> 1, hb = u & 1;
                float c  = (float)(16 * kb + 8 * hb + 2 * tig) * 0.15625f;
                float cb = c + 0.15625f;
                raA0[u] = ex2_h2f(fmaf(c, fmaf(c, -14.4269504f, B0), A0),
                                  fmaf(cb, fmaf(cb, -14.4269504f, B0), A0));
                raA1[u] = ex2_h2f(fmaf(c, fmaf(c, -14.4269504f, B1c), A1),
                                  fmaf(cb, fmaf(cb, -14.4269504f, B1c), A1));
                raB0[u] = ex2_h2f(fmaf(c, fmaf(c, -14.4269504f, B2c), A2),
                                  fmaf(cb, fmaf(cb, -14.4269504f, B2c), A2));
                raB1[u] = ex2_h2f(fmaf(c, fmaf(c, -14.4269504f, B3), A3),
                                  fmaf(cb, fmaf(cb, -14.4269504f, B3), A3));
            }

            // GEMM1 (fp16): both m-blocks share B fragments; fused epi1
            u32 hA[8][2], hB[8][2];
#pragma unroll
            for (int nb = 0; nb < 8; nb++) {
                uint4 w0 = b1p[(nb * 2 + 0) * 32];
                uint4 w1 = b1p[(nb * 2 + 1) * 32];
                float dA[4] = {0.f, 0.f, 0.f, 0.f};
                float dB[4] = {0.f, 0.f, 0.f, 0.f};
                mma_f16(dA, raA0[0], raA1[0], raA0[1], raA1[1], w0.x, w0.y);
                mma_f16(dA, raA0[2], raA1[2], raA0[3], raA1[3], w0.z, w0.w);
                mma_f16(dA, raA0[4], raA1[4], raA0[5], raA1[5], w1.x, w1.y);
                mma_f16(dA, raA0[6], raA1[6], raA0[7], raA1[7], w1.z, w1.w);
                mma_f16(dB, raB0[0], raB1[0], raB0[1], raB1[1], w0.x, w0.y);
                mma_f16(dB, raB0[2], raB1[2], raB0[3], raB1[3], w0.z, w0.w);
                mma_f16(dB, raB0[4], raB1[4], raB0[5], raB1[5], w1.x, w1.y);
                mma_f16(dB, raB0[6], raB1[6], raB0[7], raB1[7], w1.z, w1.w);
                float2 bb = *(const float2*)&bias_s[8 * nb + 2 * tig];
                hA[nb][0] = tanh_h2(dA[0] + bb.x, dA[1] + bb.y);
                hA[nb][1] = tanh_h2(dA[2] + bb.x, dA[3] + bb.y);
                hB[nb][0] = tanh_h2(dB[0] + bb.x, dB[1] + bb.y);
                hB[nb][1] = tanh_h2(dB[2] + bb.x, dB[3] + bb.y);
            }

            // GEMM2 (fp16) + epi2 + shuffle reduce + atomic scatter to vs
#pragma unroll
            for (int nb2 = 0; nb2 < 8; nb2++) {
                uint4 w0 = b2p[(nb2 * 2 + 0) * 32];
                uint4 w1 = b2p[(nb2 * 2 + 1) * 32];
                float dA[4] = {0.f, 0.f, 0.f, 0.f};
                float dB[4] = {0.f, 0.f, 0.f, 0.f};
                mma_f16(dA, hA[0][0], hA[0][1], hA[1][0], hA[1][1], w0.x, w0.y);
                mma_f16(dA, hA[2][0], hA[2][1], hA[3][0], hA[3][1], w0.z, w0.w);
                mma_f16(dA, hA[4][0], hA[4][1], hA[5][0], hA[5][1], w1.x, w1.y);
                mma_f16(dA, hA[6][0], hA[6][1], hA[7][0], hA[7][1], w1.z, w1.w);
                mma_f16(dB, hB[0][0], hB[0][1], hB[1][0], hB[1][1], w0.x, w0.y);
                mma_f16(dB, hB[2][0], hB[2][1], hB[3][0], hB[3][1], w0.z, w0.w);
                mma_f16(dB, hB[4][0], hB[4][1], hB[5][0], hB[5][1], w1.x, w1.y);
                mma_f16(dB, hB[6][0], hB[6][1], hB[7][0], hB[7][1], w1.z, w1.w);

                float2 bb = *(const float2*)&bias_s[64 + 8 * nb2 + 2 * tig];
                float2 fA0 = h2_f2(tanh_h2(dA[0] + bb.x, dA[1] + bb.y));
                float2 fA1 = h2_f2(tanh_h2(dA[2] + bb.x, dA[3] + bb.y));
                float2 fB0 = h2_f2(tanh_h2(dB[0] + bb.x, dB[1] + bb.y));
                float2 fB1 = h2_f2(tanh_h2(dB[2] + bb.x, dB[3] + bb.y));

                const int co = 8 * nb2 + 2 * tig;
                float2 xA0 = *(const float2*)&Xl[jA0 * LDA + co];
                float2 xA1 = *(const float2*)&Xl[jA1 * LDA + co];
                float2 xB0 = *(const float2*)&Xl[jB0 * LDA + co];
                float2 xB1 = pad ? make_float2(0.f, 0.f)
                                 : *(const float2*)&Xl[jB1 * LDA + co];

                float p0 = fmaf(fA0.x, xA0.x, fmaf(fA1.x, xA1.x,
                           fmaf(fB0.x, xB0.x, fB1.x * xB1.x)));
                float p1 = fmaf(fA0.y, xA0.y, fmaf(fA1.y, xA1.y,
                           fmaf(fB0.y, xB0.y, fB1.y * xB1.y)));
#pragma unroll
                for (int mk = 4; mk <= 16; mk <<= 1) {
                    p0 += __shfl_xor_sync(0xffffffffu, p0, mk);
                    p1 += __shfl_xor_sync(0xffffffffu, p1, mk);
                }
                if (g == 0) {
                    atomicAdd(&vs[ia * LDX + co],     p0);
                    atomicAdd(&vs[ia * LDX + co + 1], p1);
                }
            }
        }
        __syncthreads();

        // v = tanh(vs@Wv1+bv1) [frags]; X += v@Wv2+bv2 (all MMA)
        stage_bh(Wv1_g + wofs, B1h, tid);
        stage_bh(Wv2_g + wofs, B2h, tid);
        stage_af(vs, LDX, Af, tid);
        __syncthreads();
        mma_small<1>((const uint4*)Af, B1h, bv1_g + bofs, 0, 0, Af2, wid, lane);
        __syncthreads();
        mma_small<2>((const uint4*)Af2, B2h, bv2_g + bofs, X, LDX, 0, wid, lane);
        __syncthreads();
    }

    // ---- output head (scalar, tiny) ----
    {
        float* Wah  = scr;
        float* Wbh  = sm + OFF_B1;
        float* redh = red;
#pragma unroll
        for (int ii = 0; ii < 8; ii++)
            Wah[tid + 256 * ii] = __ldg(W1_g + tid + 256 * ii);
        if (tid < 32) {
            Wbh[tid]      = __ldg(W2_g + tid);
            Wbh[32 + tid] = __ldg(b1_g + tid);
        }
        if (tid == 0) Wbh[64] = __ldg(b2_g);
        __syncthreads();

        int a = tid >> 2, cq = (tid & 3) * 8;
        float acc[8];
#pragma unroll
        for (int j = 0; j < 8; j++) acc[j] = Wbh[32 + cq + j];
#pragma unroll 8
        for (int k = 0; k < 64; k++) {
            float xa = X[a * LDX + k];
            const float* wr = Wah + k * 32 + cq;
#pragma unroll
            for (int j = 0; j < 8; j++) acc[j] = fmaf(xa, wr[j], acc[j]);
        }
        float s = 0.0f;
#pragma unroll
        for (int j = 0; j < 8; j++)
            s = fmaf(tanhf_mufu(acc[j]), Wbh[cq + j], s);
#pragma unroll
        for (int off = 16; off > 0; off >>= 1)
            s += __shfl_xor_sync(0xffffffffu, s, off);
        if (lane == 0) redh[wid] = s;
        __syncthreads();
        if (tid == 0) {
            float tot = 0.0f;
#pragma unroll
            for (int w = 0; w < 8; w++) tot += redh[w];
            out_g[b] = tot + 64.0f * Wbh[64];
        }
    }
}

extern "C" void kernel_launch(void* const* d_in, const int* in_sizes, int n_in,
                              void* d_out, int out_size) {
    const float* r_g   = (const float*)d_in[0];
    const float* v1_g  = (const float*)d_in[1];
    const float* v2_g  = (const float*)d_in[2];
    const float* cen_g = (const float*)d_in[3];
    const float* Wx_g  = (const float*)d_in[4];
    const float* bx_g  = (const float*)d_in[5];
    const float* Wf1_g = (const float*)d_in[6];
    const float* bf1_g = (const float*)d_in[7];
    const float* Wf2_g = (const float*)d_in[8];
    const float* bf2_g = (const float*)d_in[9];
    const float* Wv1_g = (const float*)d_in[10];
    const float* bv1_g = (const float*)d_in[11];
    const float* Wv2_g = (const float*)d_in[12];
    const float* bv2_g = (const float*)d_in[13];
    const float* W1_g  = (const float*)d_in[14];
    const float* b1_g  = (const float*)d_in[15];
    const float* W2_g  = (const float*)d_in[16];
    const float* b2_g  = (const float*)d_in[17];
    float* out = (float*)d_out;
    int batch = in_sizes[0] / 192;

    cudaFuncSetAttribute(schnet_kernel,
                         cudaFuncAttributeMaxDynamicSharedMemorySize, SMEM_BYTES);
    schnet_kernel<<<batch, 256, SMEM_BYTES>>>(
        r_g, v1_g, v2_g, cen_g, Wx_g, bx_g, Wf1_g, bf1_g, Wf2_g, bf2_g,
        Wv1_g, bv1_g, Wv2_g, bv2_g, W1_g, b1_g, W2_g, b2_g, out);
}

// round 17
// speedup vs baseline: 1.1012x; 1.1012x over previous
#include <cuda_runtime.h>
#include <cuda_fp16.h>
#include <cstdint>

// ---------------------------------------------------------------------------
// SchNet fused kernel, round 17: round-15 + barrier-free tile loop via
// warp-private vs halves (plain stores; halves summed during fp16 staging).
// No red buffer, no pair barriers, no atomics. 256 thr, 2 CTAs/SM.
// ---------------------------------------------------------------------------

typedef unsigned long long u64;
typedef unsigned int u32;

#define LDA 72   // float stride: Xl
#define LDX 68   // X / vs stride

// float offsets
#define OFF_POS   0        // 256
#define OFF_BIAS  256      // 128
#define OFF_XL    384      // 64*72 = 4608
#define OFF_X     4992     // 4352
#define OFF_VS    9344     // 2 * 64*68 = 8704 (two warp-private halves)
#define OFF_B1    18048    // 2048 (fp16 frag-major weights)
#define OFF_B2    20096    // 2048
#define OFF_RED   22144    // 64 (head reduce scratch only)
#define OFF_SCR   22208    // 4096: Af frags [0..2048), aux [2048..4096)
#define SMEM_FLOATS 26304
#define SMEM_BYTES  (SMEM_FLOATS * 4)   // 105216 -> 2 CTAs/SM (210KB <= 228KB)

__device__ __forceinline__ float tanhf_mufu(float x) {
    float r; asm("tanh.approx.f32 %0, %1;" : "=f"(r) : "f"(x)); return r;
}
__device__ __forceinline__ u32 cvt_h2(float lo, float hi) {
    u32 r; asm("cvt.rn.f16x2.f32 %0, %1, %2;" : "=r"(r) : "f"(hi), "f"(lo));
    return r;
}
__device__ __forceinline__ u32 tanh_h2(float lo, float hi) {
    u32 p = cvt_h2(lo, hi), r;
    asm("tanh.approx.f16x2 %0, %1;" : "=r"(r) : "r"(p));
    return r;
}
__device__ __forceinline__ u32 ex2_h2f(float lo, float hi) {
    u32 p = cvt_h2(lo, hi), r;
    asm("ex2.approx.f16x2 %0, %1;" : "=r"(r) : "r"(p));
    return r;
}
__device__ __forceinline__ float2 h2_f2(u32 v) {
    __half2 h = *reinterpret_cast<__half2*>(&v);
    return __half22float2(h);
}
__device__ __forceinline__ void mma_f16(float (&d)[4], u32 a0, u32 a1, u32 a2,
                                        u32 a3, u32 b0, u32 b1) {
    asm("mma.sync.aligned.m16n8k16.row.col.f32.f16.f16.f32 "
        "{%0,%1,%2,%3}, {%4,%5,%6,%7}, {%8,%9}, {%0,%1,%2,%3};"
        : "+f"(d[0]), "+f"(d[1]), "+f"(d[2]), "+f"(d[3])
        : "r"(a0), "r"(a1), "r"(a2), "r"(a3), "r"(b0), "r"(b1));
}

// W[k][n] (64x64 row-major) -> fp16 frag-major B layout (proven); 256 thr
__device__ __forceinline__ void stage_bh(const float* __restrict__ g,
                                         __half* __restrict__ s, int tid) {
#pragma unroll
    for (int ii = 0; ii < 16; ii++) {
        int idx = tid + ii * 256;
        int k = idx >> 6, n = idx & 63;
        int ln = 4 * (n & 7) + ((k >> 1) & 3);
        int i = k >> 3;
        s[((((n >> 3) * 2 + (i >> 2)) * 32 + ln) * 4 + (i & 3)) * 2 + (k & 1)] =
            __float2half(__ldg(g + idx));
    }
}

// fp32 row-major S (64x64, stride lds) -> fp16 A-fragment layout
__device__ __forceinline__ void stage_af(const float* __restrict__ S, int lds,
                                         u32* __restrict__ Au, int tid) {
#pragma unroll
    for (int ii = 0; ii < 8; ii++) {
        int idx = tid + ii * 256;
        int slot = idx & 3, ln = (idx >> 2) & 31;
        int kb = (idx >> 7) & 3, mb = idx >> 9;
        int gg = ln >> 2, tg = ln & 3;
        int row = 16 * mb + gg + 8 * (slot & 1);
        int kk = 16 * kb + 2 * tg + 8 * (slot >> 1);
        Au[idx] = cvt_h2(S[row * lds + kk], S[row * lds + kk + 1]);
    }
}
// same, but sums two sources (vs halves) while staging
__device__ __forceinline__ void stage_af_sum(const float* __restrict__ S,
                                             const float* __restrict__ S2,
                                             int lds, u32* __restrict__ Au,
                                             int tid) {
#pragma unroll
    for (int ii = 0; ii < 8; ii++) {
        int idx = tid + ii * 256;
        int slot = idx & 3, ln = (idx >> 2) & 31;
        int kb = (idx >> 7) & 3, mb = idx >> 9;
        int gg = ln >> 2, tg = ln & 3;
        int row = 16 * mb + gg + 8 * (slot & 1);
        int kk = 16 * kb + 2 * tg + 8 * (slot >> 1);
        Au[idx] = cvt_h2(S[row * lds + kk] + S2[row * lds + kk],
                         S[row * lds + kk + 1] + S2[row * lds + kk + 1]);
    }
}

// 64x64 @ 64x64 fp16 MMA GEMM. 8 warps: wm = m-block, nh = n-half.
template <int EPI>
__device__ __forceinline__ void mma_small(const uint4* __restrict__ Af,
                                          const __half* __restrict__ Bh,
                                          const float* __restrict__ bias_g,
                                          float* __restrict__ C, int ldc,
                                          u32* __restrict__ AfOut,
                                          int wid, int lane) {
    const int wm = wid & 3, nh = wid >> 2;
    const int g = lane >> 2, tig = lane & 3;
    const uint4* ap = Af + wm * 128 + lane;
    uint4 A0 = ap[0], A1 = ap[32], A2 = ap[64], A3 = ap[96];
    const uint4* bp = (const uint4*)Bh + lane;
    const int r0 = 16 * wm + g, r1 = r0 + 8;
#pragma unroll
    for (int nl = 0; nl < 4; nl++) {
        const int nb = 4 * nh + nl;
        uint4 w0 = bp[(nb * 2 + 0) * 32];
        uint4 w1 = bp[(nb * 2 + 1) * 32];
        float d[4] = {0.f, 0.f, 0.f, 0.f};
        mma_f16(d, A0.x, A0.y, A0.z, A0.w, w0.x, w0.y);
        mma_f16(d, A1.x, A1.y, A1.z, A1.w, w0.z, w0.w);
        mma_f16(d, A2.x, A2.y, A2.z, A2.w, w1.x, w1.y);
        mma_f16(d, A3.x, A3.y, A3.z, A3.w, w1.z, w1.w);
        float2 bb = *(const float2*)(bias_g + 8 * nb + 2 * tig);
        if (EPI == 1) {
            u32 base = ((u32)(wm * 4 + (nb >> 1)) * 32 + (u32)lane) * 4 +
                       (u32)(nb & 1) * 2;
            AfOut[base]     = tanh_h2(d[0] + bb.x, d[1] + bb.y);
            AfOut[base + 1] = tanh_h2(d[2] + bb.x, d[3] + bb.y);
        } else {
            const int c = 8 * nb + 2 * tig;
            float2 o0 = make_float2(d[0] + bb.x, d[1] + bb.y);
            float2 o1 = make_float2(d[2] + bb.x, d[3] + bb.y);
            if (EPI == 2) {
                float2 e0 = *(float2*)&C[r0 * ldc + c];
                float2 e1 = *(float2*)&C[r1 * ldc + c];
                o0.x += e0.x; o0.y += e0.y; o1.x += e1.x; o1.y += e1.y;
            }
            *(float2*)&C[r0 * ldc + c] = o0;
            *(float2*)&C[r1 * ldc + c] = o1;
        }
    }
}

__global__ void __launch_bounds__(256, 2)
schnet_kernel(const float* __restrict__ r_g, const float* __restrict__ v1_g,
              const float* __restrict__ v2_g, const float* __restrict__ cen_g,
              const float* __restrict__ Wx_g,  const float* __restrict__ bx_g,
              const float* __restrict__ Wf1_g, const float* __restrict__ bf1_g,
              const float* __restrict__ Wf2_g, const float* __restrict__ bf2_g,
              const float* __restrict__ Wv1_g, const float* __restrict__ bv1_g,
              const float* __restrict__ Wv2_g, const float* __restrict__ bv2_g,
              const float* __restrict__ W1_g,  const float* __restrict__ b1_g,
              const float* __restrict__ W2_g,  const float* __restrict__ b2_g,
              float* __restrict__ out_g) {
    extern __shared__ float sm[];
    float*  pos    = sm + OFF_POS;
    float*  bias_s = sm + OFF_BIAS;
    float*  Xl     = sm + OFF_XL;
    float*  X      = sm + OFF_X;
    float*  vs0    = sm + OFF_VS;              // half 0
    float*  vs1    = sm + OFF_VS + 64 * LDX;   // half 1
    __half* B1h    = (__half*)(sm + OFF_B1);
    __half* B2h    = (__half*)(sm + OFF_B2);
    float*  red    = sm + OFF_RED;
    float*  scr    = sm + OFF_SCR;
    u32*    Af     = (u32*)scr;
    u32*    Af2    = (u32*)(scr + 2048);
    __half* WxH    = (__half*)(scr + 2048);   // aliases Af2; disjoint in time

    const int tid  = threadIdx.x, b = blockIdx.x;
    const int wid  = tid >> 5, lane = tid & 31;
    const int pair = wid >> 1;            // atom-within-tile (0..3)
    const int wm2  = wid & 1;             // row-half of atom
    const int g    = lane >> 2, tig = lane & 3;

    float* vsMine = wm2 ? vs1 : vs0;      // this warp's private vs half

    // ---- init ----
    if (tid < 192) pos[tid] = r_g[b * 192 + tid];
#pragma unroll
    for (int ii = 0; ii < 16; ii++) {
        int idx = tid + ii * 256;
        int a = idx >> 6, f = idx & 63;
        X[a * LDX + f] = (a < 2) ? __ldg(v1_g + f) : __ldg(v2_g + f);
    }
    __syncthreads();

    const uint4* b1p = (const uint4*)B1h + lane;
    const uint4* b2p = (const uint4*)B2h + lane;

    // lane's four row positions within the atom's 64 pair-rows
    const int mA0 = 32 * wm2 + g;
    const int mA1 = mA0 + 8;
    const int mB0 = mA0 + 16;
    const int mB1 = mA0 + 24;             // can be pad=63
    const bool pad = (mB1 == 63);

    for (int t = 0; t < 3; t++) {
        const int wofs = t * 4096, bofs = t * 64;

        // stage: Wx (fp16 B-frags), X (fp16 A-frags), Wf1/Wf2, biases
        stage_bh(Wx_g + wofs, WxH, tid);
        stage_af(X, LDX, Af, tid);
        stage_bh(Wf1_g + wofs, B1h, tid);
        stage_bh(Wf2_g + wofs, B2h, tid);
        if (tid < 64) {
            bias_s[tid]      = __ldg(bf1_g + bofs + tid);
            bias_s[64 + tid] = __ldg(bf2_g + bofs + tid);
        }
        __syncthreads();
        // Xl = X@Wx + bx (MMA)
        mma_small<0>((const uint4*)Af, WxH, bx_g + bofs, Xl, LDA, 0, wid, lane);
        __syncthreads();

        // ---- 16 tiles x 4 atoms; NO synchronization inside the loop ----
        for (int tt = 0; tt < 16; tt++) {
            const int ia = 4 * tt + pair;

            const int jA0 = mA0 + (mA0 >= ia);
            const int jA1 = mA1 + (mA1 >= ia);
            const int jB0 = mB0 + (mB0 >= ia);
            const int jB1 = pad ? 63 : mB1 + (mB1 >= ia);

            // distances + quadratic rbf coefficients
            float A0, B0, A1, B1c, A2, B2c, A3, B3;
            {
                float px = pos[3 * ia], py = pos[3 * ia + 1], pz = pos[3 * ia + 2];
                float dx, dy, dz, d;
                dx = px - pos[3 * jA0]; dy = py - pos[3 * jA0 + 1]; dz = pz - pos[3 * jA0 + 2];
                d = sqrtf(fmaf(dx, dx, fmaf(dy, dy, dz * dz)));
                A0 = -14.4269504f * d * d; B0 = 28.8539008f * d;
                dx = px - pos[3 * jA1]; dy = py - pos[3 * jA1 + 1]; dz = pz - pos[3 * jA1 + 2];
                d = sqrtf(fmaf(dx, dx, fmaf(dy, dy, dz * dz)));
                A1 = -14.4269504f * d * d; B1c = 28.8539008f * d;
                dx = px - pos[3 * jB0]; dy = py - pos[3 * jB0 + 1]; dz = pz - pos[3 * jB0 + 2];
                d = sqrtf(fmaf(dx, dx, fmaf(dy, dy, dz * dz)));
                A2 = -14.4269504f * d * d; B2c = 28.8539008f * d;
                dx = px - pos[3 * jB1]; dy = py - pos[3 * jB1 + 1]; dz = pz - pos[3 * jB1 + 2];
                d = pad ? 1e9f : sqrtf(fmaf(dx, dx, fmaf(dy, dy, dz * dz)));
                A3 = -14.4269504f * d * d; B3 = 28.8539008f * d;
            }

            // rbf into fp16x2 A-fragments
            u32 raA0[8], raA1[8], raB0[8], raB1[8];
#pragma unroll
            for (int u = 0; u < 8; u++) {
                int kb = u >> 1, hb = u & 1;
                float c  = (float)(16 * kb + 8 * hb + 2 * tig) * 0.15625f;
                float cb = c + 0.15625f;
                raA0[u] = ex2_h2f(fmaf(c, fmaf(c, -14.4269504f, B0), A0),
                                  fmaf(cb, fmaf(cb, -14.4269504f, B0), A0));
                raA1[u] = ex2_h2f(fmaf(c, fmaf(c, -14.4269504f, B1c), A1),
                                  fmaf(cb, fmaf(cb, -14.4269504f, B1c), A1));
                raB0[u] = ex2_h2f(fmaf(c, fmaf(c, -14.4269504f, B2c), A2),
                                  fmaf(cb, fmaf(cb, -14.4269504f, B2c), A2));
                raB1[u] = ex2_h2f(fmaf(c, fmaf(c, -14.4269504f, B3), A3),
                                  fmaf(cb, fmaf(cb, -14.4269504f, B3), A3));
            }

            // GEMM1 (fp16): both m-blocks share B fragments; fused epi1
            u32 hA[8][2], hB[8][2];
#pragma unroll
            for (int nb = 0; nb < 8; nb++) {
                uint4 w0 = b1p[(nb * 2 + 0) * 32];
                uint4 w1 = b1p[(nb * 2 + 1) * 32];
                float dA[4] = {0.f, 0.f, 0.f, 0.f};
                float dB[4] = {0.f, 0.f, 0.f, 0.f};
                mma_f16(dA, raA0[0], raA1[0], raA0[1], raA1[1], w0.x, w0.y);
                mma_f16(dA, raA0[2], raA1[2], raA0[3], raA1[3], w0.z, w0.w);
                mma_f16(dA, raA0[4], raA1[4], raA0[5], raA1[5], w1.x, w1.y);
                mma_f16(dA, raA0[6], raA1[6], raA0[7], raA1[7], w1.z, w1.w);
                mma_f16(dB, raB0[0], raB1[0], raB0[1], raB1[1], w0.x, w0.y);
                mma_f16(dB, raB0[2], raB1[2], raB0[3], raB1[3], w0.z, w0.w);
                mma_f16(dB, raB0[4], raB1[4], raB0[5], raB1[5], w1.x, w1.y);
                mma_f16(dB, raB0[6], raB1[6], raB0[7], raB1[7], w1.z, w1.w);
                float2 bb = *(const float2*)&bias_s[8 * nb + 2 * tig];
                hA[nb][0] = tanh_h2(dA[0] + bb.x, dA[1] + bb.y);
                hA[nb][1] = tanh_h2(dA[2] + bb.x, dA[3] + bb.y);
                hB[nb][0] = tanh_h2(dB[0] + bb.x, dB[1] + bb.y);
                hB[nb][1] = tanh_h2(dB[2] + bb.x, dB[3] + bb.y);
            }

            // GEMM2 (fp16) + epi2 + shuffle reduce + private store to vs half
#pragma unroll
            for (int nb2 = 0; nb2 < 8; nb2++) {
                uint4 w0 = b2p[(nb2 * 2 + 0) * 32];
                uint4 w1 = b2p[(nb2 * 2 + 1) * 32];
                float dA[4] = {0.f, 0.f, 0.f, 0.f};
                float dB[4] = {0.f, 0.f, 0.f, 0.f};
                mma_f16(dA, hA[0][0], hA[0][1], hA[1][0], hA[1][1], w0.x, w0.y);
                mma_f16(dA, hA[2][0], hA[2][1], hA[3][0], hA[3][1], w0.z, w0.w);
                mma_f16(dA, hA[4][0], hA[4][1], hA[5][0], hA[5][1], w1.x, w1.y);
                mma_f16(dA, hA[6][0], hA[6][1], hA[7][0], hA[7][1], w1.z, w1.w);
                mma_f16(dB, hB[0][0], hB[0][1], hB[1][0], hB[1][1], w0.x, w0.y);
                mma_f16(dB, hB[2][0], hB[2][1], hB[3][0], hB[3][1], w0.z, w0.w);
                mma_f16(dB, hB[4][0], hB[4][1], hB[5][0], hB[5][1], w1.x, w1.y);
                mma_f16(dB, hB[6][0], hB[6][1], hB[7][0], hB[7][1], w1.z, w1.w);

                float2 bb = *(const float2*)&bias_s[64 + 8 * nb2 + 2 * tig];
                float2 fA0 = h2_f2(tanh_h2(dA[0] + bb.x, dA[1] + bb.y));
                float2 fA1 = h2_f2(tanh_h2(dA[2] + bb.x, dA[3] + bb.y));
                float2 fB0 = h2_f2(tanh_h2(dB[0] + bb.x, dB[1] + bb.y));
                float2 fB1 = h2_f2(tanh_h2(dB[2] + bb.x, dB[3] + bb.y));

                const int co = 8 * nb2 + 2 * tig;
                float2 xA0 = *(const float2*)&Xl[jA0 * LDA + co];
                float2 xA1 = *(const float2*)&Xl[jA1 * LDA + co];
                float2 xB0 = *(const float2*)&Xl[jB0 * LDA + co];
                float2 xB1 = pad ? make_float2(0.f, 0.f)
                                 : *(const float2*)&Xl[jB1 * LDA + co];

                float p0 = fmaf(fA0.x, xA0.x, fmaf(fA1.x, xA1.x,
                           fmaf(fB0.x, xB0.x, fB1.x * xB1.x)));
                float p1 = fmaf(fA0.y, xA0.y, fmaf(fA1.y, xA1.y,
                           fmaf(fB0.y, xB0.y, fB1.y * xB1.y)));
#pragma unroll
                for (int mk = 4; mk <= 16; mk <<= 1) {
                    p0 += __shfl_xor_sync(0xffffffffu, p0, mk);
                    p1 += __shfl_xor_sync(0xffffffffu, p1, mk);
                }
                if (g == 0)
                    *(float2*)&vsMine[ia * LDX + co] = make_float2(p0, p1);
            }
        }
        __syncthreads();

        // v = tanh((vs0+vs1)@Wv1+bv1) [frags]; X += v@Wv2+bv2 (all MMA)
        stage_bh(Wv1_g + wofs, B1h, tid);
        stage_bh(Wv2_g + wofs, B2h, tid);
        stage_af_sum(vs0, vs1, LDX, Af, tid);
        __syncthreads();
        mma_small<1>((const uint4*)Af, B1h, bv1_g + bofs, 0, 0, Af2, wid, lane);
        __syncthreads();
        mma_small<2>((const uint4*)Af2, B2h, bv2_g + bofs, X, LDX, 0, wid, lane);
        __syncthreads();
    }

    // ---- output head (scalar, tiny) ----
    {
        float* Wah  = scr;
        float* Wbh  = sm + OFF_B1;
        float* redh = red;
#pragma unroll
        for (int ii = 0; ii < 8; ii++)
            Wah[tid + 256 * ii] = __ldg(W1_g + tid + 256 * ii);
        if (tid < 32) {
            Wbh[tid]      = __ldg(W2_g + tid);
            Wbh[32 + tid] = __ldg(b1_g + tid);
        }
        if (tid == 0) Wbh[64] = __ldg(b2_g);
        __syncthreads();

        int a = tid >> 2, cq = (tid & 3) * 8;
        float acc[8];
#pragma unroll
        for (int j = 0; j < 8; j++) acc[j] = Wbh[32 + cq + j];
#pragma unroll 8
        for (int k = 0; k < 64; k++) {
            float xa = X[a * LDX + k];
            const float* wr = Wah + k * 32 + cq;
#pragma unroll
            for (int j = 0; j < 8; j++) acc[j] = fmaf(xa, wr[j], acc[j]);
        }
        float s = 0.0f;
#pragma unroll
        for (int j = 0; j < 8; j++)
            s = fmaf(tanhf_mufu(acc[j]), Wbh[cq + j], s);
#pragma unroll
        for (int off = 16; off > 0; off >>= 1)
            s += __shfl_xor_sync(0xffffffffu, s, off);
        if (lane == 0) redh[wid] = s;
        __syncthreads();
        if (tid == 0) {
            float tot = 0.0f;
#pragma unroll
            for (int w = 0; w < 8; w++) tot += redh[w];
            out_g[b] = tot + 64.0f * Wbh[64];
        }
    }
}

extern "C" void kernel_launch(void* const* d_in, const int* in_sizes, int n_in,
                              void* d_out, int out_size) {
    const float* r_g   = (const float*)d_in[0];
    const float* v1_g  = (const float*)d_in[1];
    const float* v2_g  = (const float*)d_in[2];
    const float* cen_g = (const float*)d_in[3];
    const float* Wx_g  = (const float*)d_in[4];
    const float* bx_g  = (const float*)d_in[5];
    const float* Wf1_g = (const float*)d_in[6];
    const float* bf1_g = (const float*)d_in[7];
    const float* Wf2_g = (const float*)d_in[8];
    const float* bf2_g = (const float*)d_in[9];
    const float* Wv1_g = (const float*)d_in[10];
    const float* bv1_g = (const float*)d_in[11];
    const float* Wv2_g = (const float*)d_in[12];
    const float* bv2_g = (const float*)d_in[13];
    const float* W1_g  = (const float*)d_in[14];
    const float* b1_g  = (const float*)d_in[15];
    const float* W2_g  = (const float*)d_in[16];
    const float* b2_g  = (const float*)d_in[17];
    float* out = (float*)d_out;
    int batch = in_sizes[0] / 192;

    cudaFuncSetAttribute(schnet_kernel,
                         cudaFuncAttributeMaxDynamicSharedMemorySize, SMEM_BYTES);
    schnet_kernel<<<batch, 256, SMEM_BYTES>>>(
        r_g, v1_g, v2_g, cen_g, Wx_g, bx_g, Wf1_g, bf1_g, Wf2_g, bf2_g,
        Wv1_g, bv1_g, Wv2_g, bv2_g, W1_g, b1_g, W2_g, b2_g, out);
}